// round 1
// baseline (speedup 1.0000x reference)
#include <cuda_runtime.h>

// Problem constants
#define N_    64
#define C_    64
#define T_    300
#define V_    25
#define IC_   16
#define NS_   3
#define TC_   4            // t-values per block
#define COLS_ 100          // TC_ * V_
#define NTHREADS 256
#define NCHUNKS (N_ * (T_ / TC_))   // 64 * 75 = 4800

struct Smem {
    float WabT[NS_][64][32];     // [s][c][r]  r<16: a_w row, r>=16: b_w row   24576 B
    float GT[NS_][64][64];       // [s][c][o]                                  49152 B
    float xs[64][COLS_];         // [c][col], col = tc*25 + v                  25600 B
    float CaCb[32][TC_ * 28];    // [r][tc*28 + v]  (28-padded for float4)     14336 B
    float Pm[TC_][25][28];       // softmax rows                               11200 B
    float Msh[104];              // M per flat col
    float colA[NS_][32];         // column sums of A+graph_attn
    float absh[NS_][32];         // a_b / b_b
    float scArr[64];             // bn scale
    float shArr[64];             // bn shift incl. summed g_b
};

__global__ void __launch_bounds__(NTHREADS, 1)
tsagc_kernel(const float* __restrict__ x,
             const float* __restrict__ A,
             const float* __restrict__ GA,
             const float* __restrict__ g_w,
             const float* __restrict__ g_b,
             const float* __restrict__ a_w,
             const float* __restrict__ a_b,
             const float* __restrict__ b_w,
             const float* __restrict__ b_b,
             const float* __restrict__ bn_gamma,
             const float* __restrict__ bn_beta,
             const float* __restrict__ bn_mean,
             const float* __restrict__ bn_var,
             float* __restrict__ out)
{
    extern __shared__ float smem_raw[];
    Smem& sm = *reinterpret_cast<Smem*>(smem_raw);
    const int tid = threadIdx.x;

    // ---------------- Phase 0: stage weights / constants ----------------
    // a_w,b_w: [s][ic][c] -> WabT[s][c][ic], WabT[s][c][16+ic]
    for (int idx = tid; idx < NS_ * IC_ * 64; idx += NTHREADS) {
        int c  = idx & 63;
        int ic = (idx >> 6) & 15;
        int s  = idx >> 10;
        sm.WabT[s][c][ic]      = a_w[idx];
        sm.WabT[s][c][16 + ic] = b_w[idx];
    }
    // g_w: [s][o][c] -> GT[s][c][o]
    for (int idx = tid; idx < NS_ * 64 * 64; idx += NTHREADS) {
        int c = idx & 63;
        int o = (idx >> 6) & 63;
        int s = idx >> 12;
        sm.GT[s][c][o] = g_w[idx];
    }
    if (tid < 64) {
        float inv = rsqrtf(bn_var[tid] + 1e-5f);
        float scv = bn_gamma[tid] * inv;
        sm.scArr[tid] = scv;
        float cb = g_b[tid] + g_b[64 + tid] + g_b[128 + tid];
        sm.shArr[tid] = (cb - bn_mean[tid]) * scv + bn_beta[tid];
    }
    for (int idx = tid; idx < NS_ * IC_; idx += NTHREADS) {
        int s = idx / IC_, ic = idx % IC_;
        sm.absh[s][ic]      = a_b[idx];
        sm.absh[s][16 + ic] = b_b[idx];
    }
    for (int idx = tid; idx < NS_ * V_; idx += NTHREADS) {
        int s = idx / V_, v = idx % V_;
        float acc = 0.f;
        #pragma unroll 5
        for (int a = 0; a < V_; a++) {
            int off = (s * V_ + a) * V_ + v;
            acc += A[off] + GA[off];
        }
        sm.colA[s][v] = acc;
    }

    // ---------------- Load x chunk ----------------
    const int chunk = blockIdx.x;
    const int n  = chunk / (T_ / TC_);
    const int t0 = (chunk % (T_ / TC_)) * TC_;
    const float* xg = x + (n * 64 * T_ + t0) * V_;   // x[n][0][t0][0]
    for (int idx = tid; idx < 64 * 25; idx += NTHREADS) {
        int c = idx / 25, q = idx % 25;
        float4 val = *reinterpret_cast<const float4*>(xg + c * (T_ * V_) + q * 4);
        *reinterpret_cast<float4*>(&sm.xs[c][q * 4]) = val;
    }
    __syncthreads();

    // persistent accumulators: thread (otile = tid/25, ctile = tid%25), tid < 200
    float accum[8][4];
    #pragma unroll
    for (int k = 0; k < 8; k++)
        #pragma unroll
        for (int j = 0; j < 4; j++) accum[k][j] = 0.f;

    const int o0   = (tid / 25) * 8;   // phase-3 row base (tid<200)
    const int col0 = (tid % 25) * 4;   // column base

    for (int s = 0; s < NS_; s++) {
        // -------- Phase 1: CaCb[32][100] = Wab[s] @ xs  (4x4 tiles) --------
        if (tid < 200) {
            int r0 = (tid / 25) * 4;
            float acc[4][4];
            #pragma unroll
            for (int k = 0; k < 4; k++)
                #pragma unroll
                for (int j = 0; j < 4; j++) acc[k][j] = 0.f;
            #pragma unroll 2
            for (int c = 0; c < 64; c++) {
                float4 w  = *reinterpret_cast<const float4*>(&sm.WabT[s][c][r0]);
                float4 xv = *reinterpret_cast<const float4*>(&sm.xs[c][col0]);
                float wa[4] = {w.x, w.y, w.z, w.w};
                float xa[4] = {xv.x, xv.y, xv.z, xv.w};
                #pragma unroll
                for (int k = 0; k < 4; k++)
                    #pragma unroll
                    for (int j = 0; j < 4; j++) acc[k][j] += wa[k] * xa[j];
            }
            #pragma unroll
            for (int k = 0; k < 4; k++) {
                float bias = sm.absh[s][r0 + k];
                #pragma unroll
                for (int j = 0; j < 4; j++) {
                    int col = col0 + j;
                    int tc = col / 25, v = col % 25;
                    sm.CaCb[r0 + k][tc * 28 + v] = acc[k][j] + bias;
                }
            }
        }
        __syncthreads();

        // -------- Phase 2a: logits row, softmax, store Pm --------
        if (tid < 100) {
            int tc = tid / 25, a = tid % 25;
            int tcBase = tc * 28;
            float l[25];
            #pragma unroll
            for (int b = 0; b < 25; b++) l[b] = 0.f;
            #pragma unroll 4
            for (int ic = 0; ic < 16; ic++) {
                float cav = sm.CaCb[ic][tcBase + a];
                const float4* cb4 =
                    reinterpret_cast<const float4*>(&sm.CaCb[16 + ic][tcBase]);
                #pragma unroll
                for (int q = 0; q < 7; q++) {
                    float4 cv = cb4[q];
                    float vals[4] = {cv.x, cv.y, cv.z, cv.w};
                    #pragma unroll
                    for (int j = 0; j < 4; j++)
                        if (q * 4 + j < 25) l[q * 4 + j] += cav * vals[j];
                }
            }
            float mx = -1e30f;
            #pragma unroll
            for (int b = 0; b < 25; b++) { l[b] *= 0.0625f; mx = fmaxf(mx, l[b]); }
            float ssum = 0.f;
            #pragma unroll
            for (int b = 0; b < 25; b++) { float e = __expf(l[b] - mx); ssum += e; l[b] = e; }
            float inv = 1.f / ssum;
            #pragma unroll
            for (int b = 0; b < 25; b++) sm.Pm[tc][a][b] = l[b] * inv;
        }
        __syncthreads();

        // -------- Phase 2b: column sums -> M --------
        if (tid < 100) {
            int tc = tid / 25, b = tid % 25;
            float msum = sm.colA[s][b];
            #pragma unroll 5
            for (int a = 0; a < 25; a++) msum += sm.Pm[tc][a][b];
            sm.Msh[tc * 25 + b] = msum;
        }
        __syncthreads();

        // -------- Phase 3: Gx = g_w[s] @ xs, accum += M[col]*Gx (8x4 tiles) --------
        if (tid < 200) {
            float tacc[8][4];
            #pragma unroll
            for (int k = 0; k < 8; k++)
                #pragma unroll
                for (int j = 0; j < 4; j++) tacc[k][j] = 0.f;
            #pragma unroll 2
            for (int c = 0; c < 64; c++) {
                float4 g0 = *reinterpret_cast<const float4*>(&sm.GT[s][c][o0]);
                float4 g1 = *reinterpret_cast<const float4*>(&sm.GT[s][c][o0 + 4]);
                float4 xv = *reinterpret_cast<const float4*>(&sm.xs[c][col0]);
                float ga[8] = {g0.x, g0.y, g0.z, g0.w, g1.x, g1.y, g1.z, g1.w};
                float xa[4] = {xv.x, xv.y, xv.z, xv.w};
                #pragma unroll
                for (int k = 0; k < 8; k++)
                    #pragma unroll
                    for (int j = 0; j < 4; j++) tacc[k][j] += ga[k] * xa[j];
            }
            float m[4];
            #pragma unroll
            for (int j = 0; j < 4; j++) m[j] = sm.Msh[col0 + j];
            #pragma unroll
            for (int k = 0; k < 8; k++)
                #pragma unroll
                for (int j = 0; j < 4; j++) accum[k][j] += tacc[k][j] * m[j];
        }
        __syncthreads();
    }

    // ---------------- Epilogue: BN + residual + ReLU ----------------
    if (tid < 200) {
        #pragma unroll
        for (int k = 0; k < 8; k++) {
            int o = o0 + k;
            float scv = sm.scArr[o];
            float shv = sm.shArr[o];
            const float* xr = &sm.xs[o][col0];
            float4 res;
            res.x = fmaxf(accum[k][0] * scv + shv + xr[0], 0.f);
            res.y = fmaxf(accum[k][1] * scv + shv + xr[1], 0.f);
            res.z = fmaxf(accum[k][2] * scv + shv + xr[2], 0.f);
            res.w = fmaxf(accum[k][3] * scv + shv + xr[3], 0.f);
            float* op = out + ((n * 64 + o) * T_ + t0) * V_ + col0;
            *reinterpret_cast<float4*>(op) = res;
        }
    }
}

extern "C" void kernel_launch(void* const* d_in, const int* in_sizes, int n_in,
                              void* d_out, int out_size)
{
    const float* x        = (const float*)d_in[0];
    const float* A        = (const float*)d_in[1];
    const float* GA       = (const float*)d_in[2];
    const float* g_w      = (const float*)d_in[3];
    const float* g_b      = (const float*)d_in[4];
    const float* a_w      = (const float*)d_in[5];
    const float* a_b      = (const float*)d_in[6];
    const float* b_w      = (const float*)d_in[7];
    const float* b_b      = (const float*)d_in[8];
    const float* bn_gamma = (const float*)d_in[9];
    const float* bn_beta  = (const float*)d_in[10];
    const float* bn_mean  = (const float*)d_in[11];
    const float* bn_var   = (const float*)d_in[12];
    float* out = (float*)d_out;

    size_t smem = sizeof(Smem);
    cudaFuncSetAttribute(tsagc_kernel,
                         cudaFuncAttributeMaxDynamicSharedMemorySize, (int)smem);
    tsagc_kernel<<<NCHUNKS, NTHREADS, smem>>>(
        x, A, GA, g_w, g_b, a_w, a_b, b_w, b_b,
        bn_gamma, bn_beta, bn_mean, bn_var, out);
}

// round 2
// speedup vs baseline: 1.4876x; 1.4876x over previous
#include <cuda_runtime.h>

// Problem constants
#define N_    64
#define C_    64
#define T_    300
#define V_    25
#define IC_   16
#define NS_   3
#define TC_   12           // t-values per block
#define COLS_ 300          // TC_ * V_
#define NTHREADS 224
#define NCHUNKS (N_ * (T_ / TC_))   // 64 * 25 = 1600

struct Smem {
    float WabT[NS_][64][32];      // [s][c][r]  r<16: a_w, r>=16: b_w        24576 B
    float GT[NS_][64][64];        // [s][c][o]                               49152 B
    float xs[64][COLS_];          // [c][col], col = tc*25 + v               76800 B
    float CaCb[32][TC_ * 28];     // [r][tc*28 + v] (28-pad for float4)      43008 B
    float Pm[TC_][25][26];        // softmax rows (26-pad, scalar access)    31200 B
    float Msh[COLS_];             // M per flat col                           1200 B
    float colA[NS_][32];          // column sums of A+graph_attn
    float absh[NS_][32];          // a_b / b_b
    float scArr[64];              // bn scale
    float shArr[64];              // bn shift incl. summed g_b
};

__global__ void __launch_bounds__(NTHREADS, 1)
tsagc_kernel(const float* __restrict__ x,
             const float* __restrict__ A,
             const float* __restrict__ GA,
             const float* __restrict__ g_w,
             const float* __restrict__ g_b,
             const float* __restrict__ a_w,
             const float* __restrict__ a_b,
             const float* __restrict__ b_w,
             const float* __restrict__ b_b,
             const float* __restrict__ bn_gamma,
             const float* __restrict__ bn_beta,
             const float* __restrict__ bn_mean,
             const float* __restrict__ bn_var,
             float* __restrict__ out)
{
    extern __shared__ float smem_raw[];
    Smem& sm = *reinterpret_cast<Smem*>(smem_raw);
    const int tid = threadIdx.x;

    // ---------------- Phase 0: stage weights / constants ----------------
    for (int idx = tid; idx < NS_ * IC_ * 64; idx += NTHREADS) {
        int c  = idx & 63;
        int ic = (idx >> 6) & 15;
        int s  = idx >> 10;
        sm.WabT[s][c][ic]      = a_w[idx];
        sm.WabT[s][c][16 + ic] = b_w[idx];
    }
    for (int idx = tid; idx < NS_ * 64 * 64; idx += NTHREADS) {
        int c = idx & 63;
        int o = (idx >> 6) & 63;
        int s = idx >> 12;
        sm.GT[s][c][o] = g_w[idx];
    }
    if (tid < 64) {
        float inv = rsqrtf(bn_var[tid] + 1e-5f);
        float scv = bn_gamma[tid] * inv;
        sm.scArr[tid] = scv;
        float cb = g_b[tid] + g_b[64 + tid] + g_b[128 + tid];
        sm.shArr[tid] = (cb - bn_mean[tid]) * scv + bn_beta[tid];
    }
    for (int idx = tid; idx < NS_ * IC_; idx += NTHREADS) {
        int s = idx / IC_, ic = idx % IC_;
        sm.absh[s][ic]      = a_b[idx];
        sm.absh[s][16 + ic] = b_b[idx];
    }
    for (int idx = tid; idx < NS_ * V_; idx += NTHREADS) {
        int s = idx / V_, v = idx % V_;
        float acc = 0.f;
        #pragma unroll 5
        for (int a = 0; a < V_; a++) {
            int off = (s * V_ + a) * V_ + v;
            acc += A[off] + GA[off];
        }
        sm.colA[s][v] = acc;
    }

    // ---------------- Load x chunk (contiguous 300 floats per channel) ----
    const int chunk = blockIdx.x;
    const int n  = chunk / (T_ / TC_);
    const int t0 = (chunk % (T_ / TC_)) * TC_;
    const float* xg = x + (n * 64 * T_ + t0) * V_;
    for (int idx = tid; idx < 64 * (COLS_ / 4); idx += NTHREADS) {
        int c = idx / (COLS_ / 4), q = idx % (COLS_ / 4);
        float4 val = *reinterpret_cast<const float4*>(xg + c * (T_ * V_) + q * 4);
        *reinterpret_cast<float4*>(&sm.xs[c][q * 4]) = val;
    }
    __syncthreads();

    // persistent accumulators: thread (otile = tid/25, ctile = tid%25), tid < 200
    float accum[8][12];
    #pragma unroll
    for (int k = 0; k < 8; k++)
        #pragma unroll
        for (int j = 0; j < 12; j++) accum[k][j] = 0.f;

    const int o0   = (tid / 25) * 8;    // phase-3 row base (tid < 200)
    const int col0 = (tid % 25) * 12;   // column base (multiple of 12, 16B aligned)

    for (int s = 0; s < NS_; s++) {
        // -------- Phase 1: CaCb[32][300] = Wab[s] @ xs  (4x12 tiles) --------
        if (tid < 200) {
            int r0 = (tid / 25) * 4;
            float acc[4][12];
            #pragma unroll
            for (int k = 0; k < 4; k++)
                #pragma unroll
                for (int j = 0; j < 12; j++) acc[k][j] = 0.f;
            #pragma unroll 2
            for (int c = 0; c < 64; c++) {
                float4 w  = *reinterpret_cast<const float4*>(&sm.WabT[s][c][r0]);
                float4 x0 = *reinterpret_cast<const float4*>(&sm.xs[c][col0]);
                float4 x1 = *reinterpret_cast<const float4*>(&sm.xs[c][col0 + 4]);
                float4 x2 = *reinterpret_cast<const float4*>(&sm.xs[c][col0 + 8]);
                float wa[4] = {w.x, w.y, w.z, w.w};
                float xa[12] = {x0.x, x0.y, x0.z, x0.w, x1.x, x1.y, x1.z, x1.w,
                                x2.x, x2.y, x2.z, x2.w};
                #pragma unroll
                for (int k = 0; k < 4; k++)
                    #pragma unroll
                    for (int j = 0; j < 12; j++) acc[k][j] += wa[k] * xa[j];
            }
            #pragma unroll
            for (int k = 0; k < 4; k++) {
                float bias = sm.absh[s][r0 + k];
                #pragma unroll
                for (int j = 0; j < 12; j++) {
                    int col = col0 + j;
                    int tc = col / 25, v = col - tc * 25;
                    sm.CaCb[r0 + k][tc * 28 + v] = acc[k][j] + bias;
                }
            }
        }
        __syncthreads();

        // -------- Phase 2a: logits row, softmax, store Pm --------
        #pragma unroll
        for (int tc0 = 0; tc0 < TC_; tc0 += 8) {
            int tc = tc0 + tid / 25;
            int a  = tid % 25;
            if (tid < 200 && tc < TC_) {
                int tcBase = tc * 28;
                float l[25];
                #pragma unroll
                for (int b = 0; b < 25; b++) l[b] = 0.f;
                #pragma unroll 4
                for (int ic = 0; ic < 16; ic++) {
                    float cav = sm.CaCb[ic][tcBase + a];
                    const float4* cb4 =
                        reinterpret_cast<const float4*>(&sm.CaCb[16 + ic][tcBase]);
                    #pragma unroll
                    for (int q = 0; q < 7; q++) {
                        float4 cv = cb4[q];
                        float vals[4] = {cv.x, cv.y, cv.z, cv.w};
                        #pragma unroll
                        for (int j = 0; j < 4; j++)
                            if (q * 4 + j < 25) l[q * 4 + j] += cav * vals[j];
                    }
                }
                float mx = -1e30f;
                #pragma unroll
                for (int b = 0; b < 25; b++) { l[b] *= 0.0625f; mx = fmaxf(mx, l[b]); }
                float ssum = 0.f;
                #pragma unroll
                for (int b = 0; b < 25; b++) { float e = __expf(l[b] - mx); ssum += e; l[b] = e; }
                float inv = 1.f / ssum;
                float* pr = sm.Pm[tc][a];
                #pragma unroll
                for (int b = 0; b < 25; b++) pr[b] = l[b] * inv;
            }
        }
        __syncthreads();

        // -------- Phase 2b: column sums -> M --------
        #pragma unroll
        for (int tc0 = 0; tc0 < TC_; tc0 += 8) {
            int tc = tc0 + tid / 25;
            int b  = tid % 25;
            if (tid < 200 && tc < TC_) {
                float msum = sm.colA[s][b];
                #pragma unroll 5
                for (int a = 0; a < 25; a++) msum += sm.Pm[tc][a][b];
                sm.Msh[tc * 25 + b] = msum;
            }
        }
        __syncthreads();

        // -------- Phase 3: accum += M[col] * (g_w[s] @ xs)  (8x12 tiles) -----
        if (tid < 200) {
            float m[12];
            #pragma unroll
            for (int j = 0; j < 12; j++) m[j] = sm.Msh[col0 + j];
            #pragma unroll 2
            for (int c = 0; c < 64; c++) {
                float4 g0 = *reinterpret_cast<const float4*>(&sm.GT[s][c][o0]);
                float4 g1 = *reinterpret_cast<const float4*>(&sm.GT[s][c][o0 + 4]);
                float4 x0 = *reinterpret_cast<const float4*>(&sm.xs[c][col0]);
                float4 x1 = *reinterpret_cast<const float4*>(&sm.xs[c][col0 + 4]);
                float4 x2 = *reinterpret_cast<const float4*>(&sm.xs[c][col0 + 8]);
                float ga[8] = {g0.x, g0.y, g0.z, g0.w, g1.x, g1.y, g1.z, g1.w};
                float xm[12] = {x0.x * m[0], x0.y * m[1], x0.z * m[2],  x0.w * m[3],
                                x1.x * m[4], x1.y * m[5], x1.z * m[6],  x1.w * m[7],
                                x2.x * m[8], x2.y * m[9], x2.z * m[10], x2.w * m[11]};
                #pragma unroll
                for (int k = 0; k < 8; k++)
                    #pragma unroll
                    for (int j = 0; j < 12; j++) accum[k][j] += ga[k] * xm[j];
            }
        }
        __syncthreads();
    }

    // ---------------- Epilogue: BN + residual + ReLU ----------------
    if (tid < 200) {
        #pragma unroll
        for (int k = 0; k < 8; k++) {
            int o = o0 + k;
            float scv = sm.scArr[o];
            float shv = sm.shArr[o];
            const float* xr = &sm.xs[o][col0];
            float* op = out + ((n * 64 + o) * T_ + t0) * V_ + col0;
            #pragma unroll
            for (int q = 0; q < 3; q++) {
                float4 res;
                res.x = fmaxf(accum[k][q * 4 + 0] * scv + shv + xr[q * 4 + 0], 0.f);
                res.y = fmaxf(accum[k][q * 4 + 1] * scv + shv + xr[q * 4 + 1], 0.f);
                res.z = fmaxf(accum[k][q * 4 + 2] * scv + shv + xr[q * 4 + 2], 0.f);
                res.w = fmaxf(accum[k][q * 4 + 3] * scv + shv + xr[q * 4 + 3], 0.f);
                *reinterpret_cast<float4*>(op + q * 4) = res;
            }
        }
    }
}

extern "C" void kernel_launch(void* const* d_in, const int* in_sizes, int n_in,
                              void* d_out, int out_size)
{
    const float* x        = (const float*)d_in[0];
    const float* A        = (const float*)d_in[1];
    const float* GA       = (const float*)d_in[2];
    const float* g_w      = (const float*)d_in[3];
    const float* g_b      = (const float*)d_in[4];
    const float* a_w      = (const float*)d_in[5];
    const float* a_b      = (const float*)d_in[6];
    const float* b_w      = (const float*)d_in[7];
    const float* b_b      = (const float*)d_in[8];
    const float* bn_gamma = (const float*)d_in[9];
    const float* bn_beta  = (const float*)d_in[10];
    const float* bn_mean  = (const float*)d_in[11];
    const float* bn_var   = (const float*)d_in[12];
    float* out = (float*)d_out;

    size_t smem = sizeof(Smem);
    cudaFuncSetAttribute(tsagc_kernel,
                         cudaFuncAttributeMaxDynamicSharedMemorySize, (int)smem);
    tsagc_kernel<<<NCHUNKS, NTHREADS, smem>>>(
        x, A, GA, g_w, g_b, a_w, a_b, b_w, b_b,
        bn_gamma, bn_beta, bn_mean, bn_var, out);
}

// round 4
// speedup vs baseline: 1.6130x; 1.0843x over previous
#include <cuda_runtime.h>

// Problem constants
#define N_    64
#define C_    64
#define T_    300
#define V_    25
#define IC_   16
#define NS_   3
#define TC_   12           // t-values per block
#define COLS_ 300          // TC_ * V_
#define NTHREADS 400
#define NCHUNKS (N_ * (T_ / TC_))   // 64 * 25 = 1600

typedef unsigned long long ull;

__device__ __forceinline__ ull dup2(float v) {
    ull r; asm("mov.b64 %0, {%1, %1};" : "=l"(r) : "f"(v)); return r;
}
__device__ __forceinline__ void fma2(ull& acc, ull a, ull b) {
    asm("fma.rn.f32x2 %0, %1, %2, %0;" : "+l"(acc) : "l"(a), "l"(b));
}
__device__ __forceinline__ ull mul2(ull a, ull b) {
    ull d; asm("mul.rn.f32x2 %0, %1, %2;" : "=l"(d) : "l"(a), "l"(b)); return d;
}
__device__ __forceinline__ void unpack2(ull v, float& lo, float& hi) {
    asm("mov.b64 {%0, %1}, %2;" : "=f"(lo), "=f"(hi) : "l"(v));
}

struct Smem {
    float WabT[NS_][64][32];      // [s][c][r] r<16: a_w, r>=16: b_w       24576 B
    float GT[NS_][64][64];        // [s][c][o]                             49152 B
    float xs[64][COLS_];          // [c][col]                              76800 B
    float CaCb[32][TC_ * 28];     // [r][tc*28+v]                          43008 B
    float Pm[TC_][25][26];        // softmax probs                         31200 B
    float Msh[NS_][COLS_];        // M per subset/col                       3600 B
    float colA[NS_][32];
    float absh[NS_][32];
    float scArr[64];
    float shArr[64];
};

__global__ void __launch_bounds__(NTHREADS, 1)
tsagc_kernel(const float* __restrict__ x,
             const float* __restrict__ A,
             const float* __restrict__ GA,
             const float* __restrict__ g_w,
             const float* __restrict__ g_b,
             const float* __restrict__ a_w,
             const float* __restrict__ a_b,
             const float* __restrict__ b_w,
             const float* __restrict__ b_b,
             const float* __restrict__ bn_gamma,
             const float* __restrict__ bn_beta,
             const float* __restrict__ bn_mean,
             const float* __restrict__ bn_var,
             float* __restrict__ out)
{
    extern __shared__ float smem_raw[];
    Smem& sm = *reinterpret_cast<Smem*>(smem_raw);
    const int tid = threadIdx.x;

    // ---------------- Phase 0: stage weights / constants ----------------
    for (int idx = tid; idx < NS_ * IC_ * 64; idx += NTHREADS) {
        int c  = idx & 63;
        int ic = (idx >> 6) & 15;
        int s  = idx >> 10;
        sm.WabT[s][c][ic]      = a_w[idx];
        sm.WabT[s][c][16 + ic] = b_w[idx];
    }
    for (int idx = tid; idx < NS_ * 64 * 64; idx += NTHREADS) {
        int c = idx & 63;
        int o = (idx >> 6) & 63;
        int s = idx >> 12;
        sm.GT[s][c][o] = g_w[idx];
    }
    if (tid < 64) {
        float inv = rsqrtf(bn_var[tid] + 1e-5f);
        float scv = bn_gamma[tid] * inv;
        sm.scArr[tid] = scv;
        float cb = g_b[tid] + g_b[64 + tid] + g_b[128 + tid];
        sm.shArr[tid] = (cb - bn_mean[tid]) * scv + bn_beta[tid];
    }
    for (int idx = tid; idx < NS_ * IC_; idx += NTHREADS) {
        int s = idx / IC_, ic = idx % IC_;
        sm.absh[s][ic]      = a_b[idx];
        sm.absh[s][16 + ic] = b_b[idx];
    }
    for (int idx = tid; idx < NS_ * V_; idx += NTHREADS) {
        int s = idx / V_, v = idx % V_;
        float acc = 0.f;
        #pragma unroll 5
        for (int a = 0; a < V_; a++) {
            int off = (s * V_ + a) * V_ + v;
            acc += A[off] + GA[off];
        }
        sm.colA[s][v] = acc;
    }
    // zero CaCb pad columns (v=25..27) so f32x2 pair loads never see garbage
    for (int idx = tid; idx < 32 * TC_ * 3; idx += NTHREADS) {
        int r = idx / (TC_ * 3);
        int q = idx % (TC_ * 3);
        sm.CaCb[r][(q / 3) * 28 + 25 + (q % 3)] = 0.f;
    }

    // ---------------- Load x chunk ----------------
    const int chunk = blockIdx.x;
    const int n  = chunk / (T_ / TC_);
    const int t0 = (chunk % (T_ / TC_)) * TC_;
    const float* xg = x + (n * 64 * T_ + t0) * V_;
    for (int idx = tid; idx < 64 * (COLS_ / 4); idx += NTHREADS) {
        int c = idx / (COLS_ / 4), q = idx % (COLS_ / 4);
        float4 val = *reinterpret_cast<const float4*>(xg + c * (T_ * V_) + q * 4);
        *reinterpret_cast<float4*>(&sm.xs[c][q * 4]) = val;
    }
    __syncthreads();

    const int rg   = tid / 50;        // 0..7
    const int cg   = tid % 50;        // 0..49
    const int col0 = cg * 6;          // column base (even, 24B aligned)

    // column -> (tc,v) map for phase-1 stores
    int tcv[6], vv[6];
    #pragma unroll
    for (int j = 0; j < 6; j++) {
        int col = col0 + j;
        tcv[j] = col / 25;
        vv[j]  = col - tcv[j] * 25;
    }

    // =========== Phases 1+2 per subset: produce Msh[s][*] ===========
    for (int s = 0; s < NS_; s++) {
        // -------- Phase 1: CaCb[32][300] = Wab[s] @ xs (4x6 tiles, f32x2) ----
        {
            const int r0 = rg * 4;
            ull acc2[4][3];
            #pragma unroll
            for (int k = 0; k < 4; k++)
                #pragma unroll
                for (int j = 0; j < 3; j++) acc2[k][j] = 0ull;
            #pragma unroll 2
            for (int c = 0; c < 64; c++) {
                float4 w = *reinterpret_cast<const float4*>(&sm.WabT[s][c][r0]);
                ull wd[4] = {dup2(w.x), dup2(w.y), dup2(w.z), dup2(w.w)};
                ull x2[3];
                #pragma unroll
                for (int j = 0; j < 3; j++)
                    x2[j] = *reinterpret_cast<const ull*>(&sm.xs[c][col0 + 2 * j]);
                #pragma unroll
                for (int k = 0; k < 4; k++)
                    #pragma unroll
                    for (int j = 0; j < 3; j++) fma2(acc2[k][j], wd[k], x2[j]);
            }
            #pragma unroll
            for (int k = 0; k < 4; k++) {
                float bias = sm.absh[s][r0 + k];
                float vals[6];
                unpack2(acc2[k][0], vals[0], vals[1]);
                unpack2(acc2[k][1], vals[2], vals[3]);
                unpack2(acc2[k][2], vals[4], vals[5]);
                #pragma unroll
                for (int j = 0; j < 6; j++)
                    sm.CaCb[r0 + k][tcv[j] * 28 + vv[j]] = vals[j] + bias;
            }
        }
        __syncthreads();

        // -------- Phase 2a: logits + softmax rows (300 threads, f32x2) -------
        if (tid < 300) {
            const int tc = tid / 25, a = tid % 25;
            const int tcBase = tc * 28;
            ull l2[13];
            #pragma unroll
            for (int p = 0; p < 13; p++) l2[p] = 0ull;
            #pragma unroll 4
            for (int ic = 0; ic < 16; ic++) {
                ull cad = dup2(sm.CaCb[ic][tcBase + a]);
                const ulonglong2* cb =
                    reinterpret_cast<const ulonglong2*>(&sm.CaCb[16 + ic][tcBase]);
                #pragma unroll
                for (int q = 0; q < 6; q++) {
                    ulonglong2 cv = cb[q];
                    fma2(l2[q * 2],     cad, cv.x);
                    fma2(l2[q * 2 + 1], cad, cv.y);
                }
                ulonglong2 cv6 = cb[6];
                fma2(l2[12], cad, cv6.x);
            }
            float l[26];
            #pragma unroll
            for (int p = 0; p < 13; p++) unpack2(l2[p], l[2 * p], l[2 * p + 1]);
            float mx = -1e30f;
            #pragma unroll
            for (int b = 0; b < 25; b++) { l[b] *= 0.0625f; mx = fmaxf(mx, l[b]); }
            float ssum = 0.f;
            #pragma unroll
            for (int b = 0; b < 25; b++) { float e = __expf(l[b] - mx); ssum += e; l[b] = e; }
            float inv = 1.f / ssum;
            float* pr = sm.Pm[tc][a];
            #pragma unroll
            for (int b = 0; b < 25; b++) pr[b] = l[b] * inv;
        }
        __syncthreads();

        // -------- Phase 2b: column sums -> Msh[s] ---------------------------
        if (tid < 300) {
            const int tc = tid / 25, b = tid % 25;
            float msum = sm.colA[s][b];
            #pragma unroll 5
            for (int a = 0; a < 25; a++) msum += sm.Pm[tc][a][b];
            sm.Msh[s][tc * 25 + b] = msum;
        }
        __syncthreads();
    }

    // =========== Phase 3 (fused over subsets): 8x6 tiles, f32x2 ===========
    const int o0 = rg * 8;
    ull acc2[8][3];
    #pragma unroll
    for (int k = 0; k < 8; k++)
        #pragma unroll
        for (int j = 0; j < 3; j++) acc2[k][j] = 0ull;

    ull m2[NS_][3];
    #pragma unroll
    for (int s = 0; s < NS_; s++)
        #pragma unroll
        for (int j = 0; j < 3; j++)
            m2[s][j] = *reinterpret_cast<const ull*>(&sm.Msh[s][col0 + 2 * j]);

    #pragma unroll 2
    for (int c = 0; c < 64; c++) {
        ull x2[3];
        #pragma unroll
        for (int j = 0; j < 3; j++)
            x2[j] = *reinterpret_cast<const ull*>(&sm.xs[c][col0 + 2 * j]);
        #pragma unroll
        for (int s = 0; s < NS_; s++) {
            float4 g0 = *reinterpret_cast<const float4*>(&sm.GT[s][c][o0]);
            float4 g1 = *reinterpret_cast<const float4*>(&sm.GT[s][c][o0 + 4]);
            float ga[8] = {g0.x, g0.y, g0.z, g0.w, g1.x, g1.y, g1.z, g1.w};
            ull xm[3];
            #pragma unroll
            for (int j = 0; j < 3; j++) xm[j] = mul2(x2[j], m2[s][j]);
            #pragma unroll
            for (int k = 0; k < 8; k++) {
                ull gd = dup2(ga[k]);
                #pragma unroll
                for (int j = 0; j < 3; j++) fma2(acc2[k][j], gd, xm[j]);
            }
        }
    }

    // ---------------- Epilogue: BN + residual + ReLU ----------------
    {
        #pragma unroll
        for (int k = 0; k < 8; k++) {
            int o = o0 + k;
            float scv = sm.scArr[o];
            float shv = sm.shArr[o];
            const float* xr = &sm.xs[o][col0];
            float* op = out + (n * 64 + o) * (T_ * V_) + t0 * V_ + col0;
            float av[6];
            unpack2(acc2[k][0], av[0], av[1]);
            unpack2(acc2[k][1], av[2], av[3]);
            unpack2(acc2[k][2], av[4], av[5]);
            #pragma unroll
            for (int q = 0; q < 3; q++) {
                float2 res;
                res.x = fmaxf(av[2 * q]     * scv + shv + xr[2 * q],     0.f);
                res.y = fmaxf(av[2 * q + 1] * scv + shv + xr[2 * q + 1], 0.f);
                *reinterpret_cast<float2*>(op + 2 * q) = res;
            }
        }
    }
}

extern "C" void kernel_launch(void* const* d_in, const int* in_sizes, int n_in,
                              void* d_out, int out_size)
{
    const float* x        = (const float*)d_in[0];
    const float* A        = (const float*)d_in[1];
    const float* GA       = (const float*)d_in[2];
    const float* g_w      = (const float*)d_in[3];
    const float* g_b      = (const float*)d_in[4];
    const float* a_w      = (const float*)d_in[5];
    const float* a_b      = (const float*)d_in[6];
    const float* b_w      = (const float*)d_in[7];
    const float* b_b      = (const float*)d_in[8];
    const float* bn_gamma = (const float*)d_in[9];
    const float* bn_beta  = (const float*)d_in[10];
    const float* bn_mean  = (const float*)d_in[11];
    const float* bn_var   = (const float*)d_in[12];
    float* out = (float*)d_out;

    size_t smem = sizeof(Smem);
    cudaFuncSetAttribute(tsagc_kernel,
                         cudaFuncAttributeMaxDynamicSharedMemorySize, (int)smem);
    tsagc_kernel<<<NCHUNKS, NTHREADS, smem>>>(
        x, A, GA, g_w, g_b, a_w, a_b, b_w, b_b,
        bn_gamma, bn_beta, bn_mean, bn_var, out);
}